// round 9
// baseline (speedup 1.0000x reference)
#include <cuda_runtime.h>
#include <cuda_bf16.h>

#define N_NODES 50000
#define N_EDGES 800000
#define DIM 128

typedef unsigned long long u64;

// packed f32x2 fma: acc = a*b + acc (element-wise on 2 packed floats)
#define FMA_F32X2(acc, a, b) \
    asm("fma.rn.f32x2 %0, %1, %2, %0;" : "+l"(acc) : "l"(a), "l"(b))

// ---------------- device scratch (no allocations allowed) ----------------
__device__ int   g_count[N_NODES];
__device__ int   g_rowptr[N_NODES + 1];
__device__ int   g_esrc[N_EDGES];
__device__ float g_agg[N_NODES * DIM];
__device__ float g_h1[N_NODES * DIM];
__device__ float g_h2[N_NODES * DIM];
__device__ float g_s[N_NODES * DIM];     // partial sums (self-GEMM output)

// ---------------- CSR build ----------------
__global__ void zero_count_kernel() {
    int i = blockIdx.x * blockDim.x + threadIdx.x;
    if (i < N_NODES) g_count[i] = 0;
}

__global__ void hist_kernel(const int* __restrict__ dst) {
    int e = blockIdx.x * blockDim.x + threadIdx.x;
    if (e < N_EDGES) {
        unsigned d = (unsigned)dst[e];
        if (d < N_NODES) atomicAdd(&g_count[d], 1);
    }
}

// single-block scan: shfl warp-scan
__global__ void scan_kernel() {
    __shared__ int wsum[32];
    __shared__ int carry_s;
    int t = threadIdx.x, lane = t & 31, w = t >> 5;
    if (t == 0) { carry_s = 0; g_rowptr[0] = 0; }
    __syncthreads();
    for (int base = 0; base < N_NODES; base += 1024) {
        int v = (base + t < N_NODES) ? g_count[base + t] : 0;
        int s = v;
#pragma unroll
        for (int off = 1; off < 32; off <<= 1) {
            int x = __shfl_up_sync(0xFFFFFFFFu, s, off);
            if (lane >= off) s += x;
        }
        if (lane == 31) wsum[w] = s;
        __syncthreads();
        if (w == 0) {
            int ws = wsum[lane];
#pragma unroll
            for (int off = 1; off < 32; off <<= 1) {
                int x = __shfl_up_sync(0xFFFFFFFFu, ws, off);
                if (lane >= off) ws += x;
            }
            wsum[lane] = ws;
        }
        __syncthreads();
        int excl_warp = (w == 0) ? 0 : wsum[w - 1];
        int total = wsum[31];
        if (base + t < N_NODES) g_rowptr[base + t + 1] = carry_s + excl_warp + s;
        __syncthreads();
        if (t == 0) carry_s += total;
        __syncthreads();
    }
}

__global__ void cursor_kernel() {
    int i = blockIdx.x * blockDim.x + threadIdx.x;
    if (i < N_NODES) g_count[i] = g_rowptr[i];
}

__global__ void scatter_kernel(const int* __restrict__ src, const int* __restrict__ dst) {
    int e = blockIdx.x * blockDim.x + threadIdx.x;
    if (e < N_EDGES) {
        unsigned d = (unsigned)dst[e];
        unsigned s = (unsigned)src[e];
        if (d < N_NODES && s < N_NODES) {
            int pos = atomicAdd(&g_count[d], 1);
            if ((unsigned)pos < N_EDGES) g_esrc[pos] = (int)s;
        }
    }
}

// ---------------- mean aggregation: one warp per node ----------------
template <int HSEL>
__global__ void aggregate_kernel(const float* __restrict__ hext) {
    const float* __restrict__ h =
        (HSEL == 0) ? hext : ((HSEL == 1) ? (const float*)g_h1 : (const float*)g_h2);
    int warp = (blockIdx.x * blockDim.x + threadIdx.x) >> 5;
    int lane = threadIdx.x & 31;
    if (warp >= N_NODES) return;
    int beg = g_rowptr[warp];
    int end = g_rowptr[warp + 1];
    float ax = 0.f, ay = 0.f, az = 0.f, aw = 0.f;
    for (int i = beg; i < end; i++) {
        int s = g_esrc[i];
        float4 v = *reinterpret_cast<const float4*>(&h[(size_t)s * DIM + lane * 4]);
        ax += v.x; ay += v.y; az += v.z; aw += v.w;
    }
    float inv = (end > beg) ? (1.0f / (float)(end - beg)) : 0.0f;
    float4 r; r.x = ax * inv; r.y = ay * inv; r.z = az * inv; r.w = aw * inv;
    *reinterpret_cast<float4*>(&g_agg[(size_t)warp * DIM + lane * 4]) = r;
}

// ---------------- half-GEMM: out = [opt act]( in @ W [+ bias | + g_s partial] ) ----
// K = 128 (single source buffer). Block = 256 threads, tile J=64 nodes x OUT cols,
// K tiled by KT=64. Packed f32x2 accumulation (neutral vs FFMA, kept as-is).
// HSEL: 0=ext, 1=g_h1, 2=g_h2, 3=g_agg.  DSEL: 0=ext, 1=g_h1, 2=g_h2, 3=g_s.
// ADD=false: out = in@W + bias.  ADD=true: out = act(g_s + in@W).
template <int OUT, bool RELU, bool ADD, int HSEL, int DSEL>
__global__ __launch_bounds__(256)
void gemm_kernel(const float* __restrict__ hinext,
                 const float* __restrict__ W,
                 const float* __restrict__ bias, float* __restrict__ outext) {
    const float* __restrict__ hin =
        (HSEL == 0) ? hinext :
        (HSEL == 1) ? (const float*)g_h1 :
        (HSEL == 2) ? (const float*)g_h2 : (const float*)g_agg;
    float* __restrict__ out =
        (DSEL == 0) ? outext :
        (DSEL == 1) ? (float*)g_h1 :
        (DSEL == 2) ? (float*)g_h2 : (float*)g_s;

    constexpr int KT   = 64;
    constexpr int J    = 64;
    constexpr int IPAD = J + 1;
    constexpr int WC   = OUT / 8;          // cols per warp (16 / 8)
    constexpr int WP   = WC / 2;           // f32x2 col-pairs per warp

    extern __shared__ float smem[];
    float* wT  = smem;                     // [KT][OUT]
    float* inT = smem + KT * OUT;          // [KT][IPAD]
    float* bs  = inT + KT * IPAD;          // [OUT]

    const int t     = threadIdx.x;
    const int lane  = t & 31;
    const int wid   = t >> 5;
    const int wcol0 = wid * WC;
    const int node0 = blockIdx.x * J;

    if (!ADD && t < OUT) bs[t] = bias[t];

    u64 acc2[2][WP];
#pragma unroll
    for (int ni = 0; ni < 2; ni++)
#pragma unroll
        for (int p = 0; p < WP; p++) acc2[ni][p] = 0ull;

    for (int kt = 0; kt < 2; kt++) {
        const int k0 = kt * KT;
        // ---- weight tile rows k0..k0+63 ----
        {
            const float4* wsrc = reinterpret_cast<const float4*>(W + (size_t)k0 * OUT);
            float4* wdst = reinterpret_cast<float4*>(wT);
            constexpr int NW4 = KT * OUT / 4;
#pragma unroll
            for (int i = t; i < NW4; i += 256) wdst[i] = wsrc[i];
        }
        // ---- input tile transposed ----
        {
            const float4 z4 = make_float4(0.f, 0.f, 0.f, 0.f);
#pragma unroll
            for (int i = t; i < J * (KT / 4); i += 256) {
                int j  = i >> 4;
                int k4 = i & 15;
                int n  = node0 + j;
                float4 v = (n < N_NODES)
                    ? *reinterpret_cast<const float4*>(&hin[(size_t)n * DIM + k0 + k4 * 4])
                    : z4;
                int kb = k4 * 4;
                inT[(kb + 0) * IPAD + j] = v.x;
                inT[(kb + 1) * IPAD + j] = v.y;
                inT[(kb + 2) * IPAD + j] = v.z;
                inT[(kb + 3) * IPAD + j] = v.w;
            }
        }
        __syncthreads();

#pragma unroll 4
        for (int k = 0; k < KT; k++) {
            float a0 = inT[k * IPAD + lane];
            float a1 = inT[k * IPAD + 32 + lane];
            unsigned ai0 = __float_as_uint(a0), ai1 = __float_as_uint(a1);
            u64 a0p, a1p;
            asm("mov.b64 %0, {%1, %1};" : "=l"(a0p) : "r"(ai0));
            asm("mov.b64 %0, {%1, %1};" : "=l"(a1p) : "r"(ai1));
            const u64* w2 = reinterpret_cast<const u64*>(&wT[k * OUT + wcol0]);
#pragma unroll
            for (int p = 0; p < WP; p++) {
                u64 wv = w2[p];
                FMA_F32X2(acc2[0][p], a0p, wv);
                FMA_F32X2(acc2[1][p], a1p, wv);
            }
        }
        __syncthreads();
    }

    // ---- epilogue ----
#pragma unroll
    for (int ni = 0; ni < 2; ni++) {
        int n = node0 + lane + ni * 32;
        if (n < N_NODES) {
#pragma unroll
            for (int c4 = 0; c4 < WC / 4; c4++) {
                unsigned u0, u1, u2, u3;
                asm("mov.b64 {%0, %1}, %2;" : "=r"(u0), "=r"(u1) : "l"(acc2[ni][c4 * 2]));
                asm("mov.b64 {%0, %1}, %2;" : "=r"(u2), "=r"(u3) : "l"(acc2[ni][c4 * 2 + 1]));
                float4 r;
                if (ADD) {
                    float4 s4 = *reinterpret_cast<const float4*>(
                        &g_s[(size_t)n * OUT + wcol0 + c4 * 4]);
                    r.x = __uint_as_float(u0) + s4.x;
                    r.y = __uint_as_float(u1) + s4.y;
                    r.z = __uint_as_float(u2) + s4.z;
                    r.w = __uint_as_float(u3) + s4.w;
                } else {
                    r.x = __uint_as_float(u0) + bs[wcol0 + c4 * 4 + 0];
                    r.y = __uint_as_float(u1) + bs[wcol0 + c4 * 4 + 1];
                    r.z = __uint_as_float(u2) + bs[wcol0 + c4 * 4 + 2];
                    r.w = __uint_as_float(u3) + bs[wcol0 + c4 * 4 + 3];
                }
                if (RELU) {
                    r.x = fmaxf(r.x, 0.f); r.y = fmaxf(r.y, 0.f);
                    r.z = fmaxf(r.z, 0.f); r.w = fmaxf(r.w, 0.f);
                }
                *reinterpret_cast<float4*>(&out[(size_t)n * OUT + wcol0 + c4 * 4]) = r;
            }
        }
    }
}

// ---------------- host launcher ----------------
extern "C" void kernel_launch(void* const* d_in, const int* in_sizes, int n_in,
                              void* d_out, int out_size) {
    // size-class input identification (ordering-agnostic)
    const float* x = nullptr;
    const int*   edge[2] = {nullptr, nullptr};
    const float* w16[4]  = {nullptr, nullptr, nullptr, nullptr};
    const float* w8[2]   = {nullptr, nullptr};
    const float* b128[2] = {nullptr, nullptr};
    const float* b2 = nullptr;
    int ne = 0, n16 = 0, n8 = 0, nb = 0;
    int x_slot = -1;

    for (int i = 0; i < n_in && i < 12; i++) {
        int sz = in_sizes[i];
        if (sz == N_NODES * DIM)      { x = (const float*)d_in[i]; x_slot = i; }
        else if (sz == N_EDGES)       { if (ne < 2)  edge[ne++] = (const int*)d_in[i]; }
        else if (sz == DIM * DIM)     { if (n16 < 4) w16[n16++] = (const float*)d_in[i]; }
        else if (sz == DIM * 64)      { if (n8 < 2)  w8[n8++]   = (const float*)d_in[i]; }
        else if (sz == DIM)           { if (nb < 2)  b128[nb++] = (const float*)d_in[i]; }
        else if (sz == 64)            { b2 = (const float*)d_in[i]; }
    }

    const float *Ws0, *Wn0, *b0, *Ws1, *Wn1, *b1, *Ws2, *Wn2;
    const int *src, *dst;
    if (x_slot == 0) {
        src = edge[0]; dst = edge[1];
        Ws0 = w16[0]; Wn0 = w16[1]; Ws1 = w16[2]; Wn1 = w16[3];
        Ws2 = w8[0];  Wn2 = w8[1];
    } else {
        dst = edge[0]; src = edge[1];
        Wn0 = w16[0]; Wn1 = w16[1]; Ws0 = w16[2]; Ws1 = w16[3];
        Wn2 = w8[0];  Ws2 = w8[1];
    }
    b0 = b128[0]; b1 = b128[1];
    float* out = (float*)d_out;

    const int SMEM128 = (64 * 128 + 64 * 65 + 128) * 4;   // 49920 B
    const int SMEM64  = (64 * 64 + 64 * 65 + 64) * 4;     // 33280 B
    cudaFuncSetAttribute(gemm_kernel<128, false, false, 0, 3>,
                         cudaFuncAttributeMaxDynamicSharedMemorySize, SMEM128);
    cudaFuncSetAttribute(gemm_kernel<128, true,  true,  3, 1>,
                         cudaFuncAttributeMaxDynamicSharedMemorySize, SMEM128);
    cudaFuncSetAttribute(gemm_kernel<128, false, false, 1, 3>,
                         cudaFuncAttributeMaxDynamicSharedMemorySize, SMEM128);
    cudaFuncSetAttribute(gemm_kernel<128, true,  true,  3, 2>,
                         cudaFuncAttributeMaxDynamicSharedMemorySize, SMEM128);
    cudaFuncSetAttribute(gemm_kernel<64,  false, false, 2, 3>,
                         cudaFuncAttributeMaxDynamicSharedMemorySize, SMEM64);
    cudaFuncSetAttribute(gemm_kernel<64,  false, true,  3, 0>,
                         cudaFuncAttributeMaxDynamicSharedMemorySize, SMEM64);

    // lazily-created aux stream + events (not device memory; capture-legal)
    static cudaStream_t s1 = nullptr;
    static cudaEvent_t evFork = nullptr, evS0, evS1, evS2, evN0, evN1;
    if (!s1) {
        cudaStreamCreateWithFlags(&s1, cudaStreamNonBlocking);
        cudaEventCreateWithFlags(&evFork, cudaEventDisableTiming);
        cudaEventCreateWithFlags(&evS0, cudaEventDisableTiming);
        cudaEventCreateWithFlags(&evS1, cudaEventDisableTiming);
        cudaEventCreateWithFlags(&evS2, cudaEventDisableTiming);
        cudaEventCreateWithFlags(&evN0, cudaEventDisableTiming);
        cudaEventCreateWithFlags(&evN1, cudaEventDisableTiming);
    }
    cudaStream_t s0 = (cudaStream_t)0;   // captured legacy stream

    const int AGG_BLOCKS  = (N_NODES * 32 + 255) / 256;
    const int GEMM_BLOCKS = (N_NODES + 63) / 64;

    // fork s1 from the capture stream
    cudaEventRecord(evFork, s0);
    cudaStreamWaitEvent(s1, evFork, 0);

    // ---- s1: self0 = x @ Ws0 + b0 -> g_s (independent of CSR/agg) ----
    gemm_kernel<128, false, false, 0, 3><<<GEMM_BLOCKS, 256, SMEM128, s1>>>(x, Ws0, b0, nullptr);
    cudaEventRecord(evS0, s1);

    // ---- s0: CSR build + agg0 (concurrent with self0) ----
    zero_count_kernel<<<(N_NODES + 255) / 256, 256, 0, s0>>>();
    hist_kernel<<<(N_EDGES + 255) / 256, 256, 0, s0>>>(dst);
    scan_kernel<<<1, 1024, 0, s0>>>();
    cursor_kernel<<<(N_NODES + 255) / 256, 256, 0, s0>>>();
    scatter_kernel<<<(N_EDGES + 255) / 256, 256, 0, s0>>>(src, dst);
    aggregate_kernel<0><<<AGG_BLOCKS, 256, 0, s0>>>(x);

    // ---- join: neigh0 = relu(g_s + agg @ Wn0) -> g_h1 ----
    cudaStreamWaitEvent(s0, evS0, 0);
    gemm_kernel<128, true, true, 3, 1><<<GEMM_BLOCKS, 256, SMEM128, s0>>>(nullptr, Wn0, nullptr, nullptr);
    cudaEventRecord(evN0, s0);

    // ---- layer 1: self1 on s1 || agg1 on s0 ----
    cudaStreamWaitEvent(s1, evN0, 0);
    gemm_kernel<128, false, false, 1, 3><<<GEMM_BLOCKS, 256, SMEM128, s1>>>(nullptr, Ws1, b1, nullptr);
    cudaEventRecord(evS1, s1);
    aggregate_kernel<1><<<AGG_BLOCKS, 256, 0, s0>>>(nullptr);
    cudaStreamWaitEvent(s0, evS1, 0);
    gemm_kernel<128, true, true, 3, 2><<<GEMM_BLOCKS, 256, SMEM128, s0>>>(nullptr, Wn1, nullptr, nullptr);
    cudaEventRecord(evN1, s0);

    // ---- layer 2: self2 on s1 || agg2 on s0; final write to d_out ----
    cudaStreamWaitEvent(s1, evN1, 0);
    gemm_kernel<64, false, false, 2, 3><<<GEMM_BLOCKS, 256, SMEM64, s1>>>(nullptr, Ws2, b2, nullptr);
    cudaEventRecord(evS2, s1);
    aggregate_kernel<2><<<AGG_BLOCKS, 256, 0, s0>>>(nullptr);
    cudaStreamWaitEvent(s0, evS2, 0);
    gemm_kernel<64, false, true, 3, 0><<<GEMM_BLOCKS, 256, SMEM64, s0>>>(nullptr, Wn2, nullptr, out);
}

// round 10
// speedup vs baseline: 1.7286x; 1.7286x over previous
#include <cuda_runtime.h>
#include <cuda_bf16.h>
#include <cstdint>

#define N_NODES 50000
#define N_EDGES 800000
#define DIM 128

// ---------------- device scratch (no allocations allowed) ----------------
__device__ int   g_count[N_NODES];
__device__ int   g_rowptr[N_NODES + 1];
__device__ int   g_esrc[N_EDGES];
__device__ int   g_bsum[256];
__device__ int   g_boff[256];
__device__ float g_agg[N_NODES * DIM];
__device__ float g_h1[N_NODES * DIM];
__device__ float g_h2[N_NODES * DIM];
__device__ float g_wt0[256 * 128];     // tf32-rounded [Wself0;Wneigh0]
__device__ float g_wt1[256 * 128];
__device__ float g_wt2[256 * 64];

__device__ __forceinline__ uint32_t f2tf32(float f) {
    uint32_t u;
    asm("cvt.rna.tf32.f32 %0, %1;" : "=r"(u) : "f"(f));
    return u;
}

#define MMA_TF32(c, a, b0, b1)                                               \
    asm volatile("mma.sync.aligned.m16n8k8.row.col.f32.tf32.tf32.f32 "       \
        "{%0,%1,%2,%3}, {%4,%5,%6,%7}, {%8,%9}, {%0,%1,%2,%3};"              \
        : "+f"((c)[0]), "+f"((c)[1]), "+f"((c)[2]), "+f"((c)[3])             \
        : "r"((a)[0]), "r"((a)[1]), "r"((a)[2]), "r"((a)[3]),                \
          "r"(b0), "r"(b1))

// ---------------- weight pre-conversion: [Wself;Wneigh] -> tf32 ----------------
template <int OUT, int LSEL>
__global__ void convw_kernel(const float* __restrict__ Ws, const float* __restrict__ Wn) {
    float* dst = (LSEL == 0) ? g_wt0 : (LSEL == 1) ? g_wt1 : g_wt2;
    int i = blockIdx.x * blockDim.x + threadIdx.x;
    if (i < 256 * OUT) {
        int k = i / OUT, o = i % OUT;
        float v = (k < 128) ? Ws[k * OUT + o] : Wn[(k - 128) * OUT + o];
        dst[i] = __uint_as_float(f2tf32(v));
    }
}

// ---------------- CSR build ----------------
__global__ void zero_count_kernel() {
    int i = blockIdx.x * blockDim.x + threadIdx.x;
    if (i < N_NODES) g_count[i] = 0;
}

__global__ void hist_kernel(const int* __restrict__ dst) {
    int e = blockIdx.x * blockDim.x + threadIdx.x;
    if (e < N_EDGES) {
        unsigned d = (unsigned)dst[e];
        if (d < N_NODES) atomicAdd(&g_count[d], 1);
    }
}

// block-wide inclusive scan over 256 threads (8 warps)
__device__ __forceinline__ int block_incl_scan256(int v, int* wsum) {
    int lane = threadIdx.x & 31, w = threadIdx.x >> 5;
    int s = v;
#pragma unroll
    for (int off = 1; off < 32; off <<= 1) {
        int x = __shfl_up_sync(0xFFFFFFFFu, s, off);
        if (lane >= off) s += x;
    }
    if (lane == 31) wsum[w] = s;
    __syncthreads();
    if (w == 0) {
        int ws = (lane < 8) ? wsum[lane] : 0;
#pragma unroll
        for (int off = 1; off < 8; off <<= 1) {
            int x = __shfl_up_sync(0xFFFFFFFFu, ws, off);
            if (lane >= off) ws += x;
        }
        if (lane < 8) wsum[lane] = ws;
    }
    __syncthreads();
    return s + ((w > 0) ? wsum[w - 1] : 0);
}

// 3-kernel chip-wide scan of g_count -> g_rowptr
__global__ void reduce_counts_kernel() {       // 196 blocks x 256
    __shared__ int wsum[8];
    int i = blockIdx.x * 256 + threadIdx.x;
    int v = (i < N_NODES) ? g_count[i] : 0;
    int incl = block_incl_scan256(v, wsum);
    if (threadIdx.x == 255) g_bsum[blockIdx.x] = incl;
}

__global__ void scan_partials_kernel() {       // 1 block x 256
    __shared__ int wsum[8];
    int t = threadIdx.x;
    int v = (t < 196) ? g_bsum[t] : 0;
    int incl = block_incl_scan256(v, wsum);
    if (t < 196) g_boff[t] = incl - v;         // exclusive block offset
}

__global__ void block_scan_kernel() {          // 196 blocks x 256
    __shared__ int wsum[8];
    int i = blockIdx.x * 256 + threadIdx.x;
    int v = (i < N_NODES) ? g_count[i] : 0;
    int incl = block_incl_scan256(v, wsum);
    if (i < N_NODES) g_rowptr[i + 1] = g_boff[blockIdx.x] + incl;
    if (i == 0) g_rowptr[0] = 0;
}

__global__ void cursor_kernel() {
    int i = blockIdx.x * blockDim.x + threadIdx.x;
    if (i < N_NODES) g_count[i] = g_rowptr[i];
}

__global__ void scatter_kernel(const int* __restrict__ src, const int* __restrict__ dst) {
    int e = blockIdx.x * blockDim.x + threadIdx.x;
    if (e < N_EDGES) {
        unsigned d = (unsigned)dst[e];
        unsigned s = (unsigned)src[e];
        if (d < N_NODES && s < N_NODES) {
            int pos = atomicAdd(&g_count[d], 1);
            if ((unsigned)pos < N_EDGES) g_esrc[pos] = (int)s;
        }
    }
}

// ---------------- mean aggregation: one warp per node ----------------
template <int HSEL>
__global__ void aggregate_kernel(const float* __restrict__ hext) {
    const float* __restrict__ h =
        (HSEL == 0) ? hext : ((HSEL == 1) ? (const float*)g_h1 : (const float*)g_h2);
    int warp = (blockIdx.x * blockDim.x + threadIdx.x) >> 5;
    int lane = threadIdx.x & 31;
    if (warp >= N_NODES) return;
    int beg = g_rowptr[warp];
    int end = g_rowptr[warp + 1];
    float ax = 0.f, ay = 0.f, az = 0.f, aw = 0.f;
    for (int i = beg; i < end; i++) {
        int s = g_esrc[i];
        float4 v = *reinterpret_cast<const float4*>(&h[(size_t)s * DIM + lane * 4]);
        ax += v.x; ay += v.y; az += v.z; aw += v.w;
    }
    float inv = (end > beg) ? (1.0f / (float)(end - beg)) : 0.0f;
    float4 r; r.x = ax * inv; r.y = ay * inv; r.z = az * inv; r.w = aw * inv;
    *reinterpret_cast<float4*>(&g_agg[(size_t)warp * DIM + lane * 4]) = r;
}

// ---------------- fused GEMM v5: tf32 tensor-core mma ----------------
// out[n][o] = act( sum_{k<256} cat[n][k] * Wt[k][o] + b[o] ), cat = [hin | g_agg].
// Block: 256 threads (8 warps). Block tile: 128 nodes x OUT. K chunk KC = 32.
// Warp grid 4(M) x 2(N): warp tile 32 nodes x OUT/2 cols =
//   2 m-subtiles(16) x NS n-subtiles(8), mma.sync.m16n8k8 tf32.
// Weights pre-converted to tf32 (g_wt*); activations cvt.rna in-register.
// smem: As[128][36] (pad-36: frag loads bank-free), Bs[32][OUT+8] (pad-8), bs[OUT].
template <int OUT, bool RELU, int HSEL, int DSEL, int WSEL>
__global__ __launch_bounds__(256)
void gemm_tc_kernel(const float* __restrict__ hinext,
                    const float* __restrict__ bias, float* __restrict__ outext) {
    const float* __restrict__ hin =
        (HSEL == 0) ? hinext : ((HSEL == 1) ? (const float*)g_h1 : (const float*)g_h2);
    float* __restrict__ out =
        (DSEL == 0) ? outext : ((DSEL == 1) ? (float*)g_h1 : (float*)g_h2);
    const float* __restrict__ Wt =
        (WSEL == 0) ? g_wt0 : (WSEL == 1) ? g_wt1 : g_wt2;

    constexpr int AP = 36;             // A row pad
    constexpr int BP = OUT + 8;        // B row pad
    constexpr int NS = OUT / 16;       // n-subtiles per warp (8 / 4)

    extern __shared__ float smem[];
    float* As = smem;                  // [128][AP]
    float* Bs = smem + 128 * AP;       // [32][BP]
    float* bs = Bs + 32 * BP;          // [OUT]

    const int tid   = threadIdx.x;
    const int lane  = tid & 31;
    const int wid   = tid >> 5;
    const int g     = lane >> 2;       // groupID 0..7
    const int t4    = lane & 3;        // threadID_in_group 0..3
    const int warpM = wid & 3;
    const int warpN = wid >> 2;
    const int node0 = blockIdx.x * 128;

    if (tid < OUT) bs[tid] = bias[tid];

    float acc[2][NS][4];
#pragma unroll
    for (int ms = 0; ms < 2; ms++)
#pragma unroll
        for (int ns = 0; ns < NS; ns++)
#pragma unroll
            for (int c = 0; c < 4; c++) acc[ms][ns][c] = 0.f;

    for (int kt = 0; kt < 8; kt++) {
        const int k0 = kt * 32;
        // ---- stage A: cat[node0..node0+127][k0..k0+31] ----
        {
            const float* srcb = (k0 < 128) ? hin : (const float*)g_agg;
            const int koff = (k0 < 128) ? k0 : (k0 - 128);
            const float4 z4 = make_float4(0.f, 0.f, 0.f, 0.f);
#pragma unroll
            for (int i = tid; i < 1024; i += 256) {     // 128 rows x 8 float4
                int j  = i >> 3;
                int k4 = i & 7;
                int n  = node0 + j;
                float4 v = (n < N_NODES)
                    ? *reinterpret_cast<const float4*>(&srcb[(size_t)n * DIM + koff + k4 * 4])
                    : z4;
                float* d = &As[j * AP + k4 * 4];
                d[0] = v.x; d[1] = v.y; d[2] = v.z; d[3] = v.w;
            }
        }
        // ---- stage B: Wt[k0..k0+31][0..OUT) (already tf32) ----
        {
            constexpr int N4 = 32 * OUT / 4;
#pragma unroll
            for (int i = tid; i < N4; i += 256) {
                int kk = i / (OUT / 4);
                int n4 = i % (OUT / 4);
                float4 wv = *reinterpret_cast<const float4*>(&Wt[(size_t)(k0 + kk) * OUT + n4 * 4]);
                *reinterpret_cast<float4*>(&Bs[kk * BP + n4 * 4]) = wv;
            }
        }
        __syncthreads();

        // ---- 4 mma k-steps over this 32-chunk ----
#pragma unroll
        for (int ks = 0; ks < 4; ks++) {
            const int kb = ks * 8;
            uint32_t a[2][4];
#pragma unroll
            for (int ms = 0; ms < 2; ms++) {
                int r = warpM * 32 + ms * 16 + g;
                a[ms][0] = f2tf32(As[r * AP + kb + t4]);
                a[ms][1] = f2tf32(As[(r + 8) * AP + kb + t4]);
                a[ms][2] = f2tf32(As[r * AP + kb + t4 + 4]);
                a[ms][3] = f2tf32(As[(r + 8) * AP + kb + t4 + 4]);
            }
#pragma unroll
            for (int ns = 0; ns < NS; ns++) {
                int c = warpN * (OUT / 2) + ns * 8 + g;
                uint32_t b0 = __float_as_uint(Bs[(kb + t4) * BP + c]);
                uint32_t b1 = __float_as_uint(Bs[(kb + t4 + 4) * BP + c]);
                MMA_TF32(acc[0][ns], a[0], b0, b1);
                MMA_TF32(acc[1][ns], a[1], b0, b1);
            }
        }
        __syncthreads();
    }

    // ---- epilogue: bias + act + float2 stores ----
#pragma unroll
    for (int ms = 0; ms < 2; ms++) {
#pragma unroll
        for (int ns = 0; ns < NS; ns++) {
            int col  = warpN * (OUT / 2) + ns * 8 + t4 * 2;
            int row0 = node0 + warpM * 32 + ms * 16 + g;
            int row1 = row0 + 8;
            float bx = bs[col], by = bs[col + 1];
            if (row0 < N_NODES) {
                float2 r;
                r.x = acc[ms][ns][0] + bx;
                r.y = acc[ms][ns][1] + by;
                if (RELU) { r.x = fmaxf(r.x, 0.f); r.y = fmaxf(r.y, 0.f); }
                *reinterpret_cast<float2*>(&out[(size_t)row0 * OUT + col]) = r;
            }
            if (row1 < N_NODES) {
                float2 r;
                r.x = acc[ms][ns][2] + bx;
                r.y = acc[ms][ns][3] + by;
                if (RELU) { r.x = fmaxf(r.x, 0.f); r.y = fmaxf(r.y, 0.f); }
                *reinterpret_cast<float2*>(&out[(size_t)row1 * OUT + col]) = r;
            }
        }
    }
}

// ---------------- host launcher ----------------
extern "C" void kernel_launch(void* const* d_in, const int* in_sizes, int n_in,
                              void* d_out, int out_size) {
    // size-class input identification (ordering-agnostic)
    const float* x = nullptr;
    const int*   edge[2] = {nullptr, nullptr};
    const float* w16[4]  = {nullptr, nullptr, nullptr, nullptr};
    const float* w8[2]   = {nullptr, nullptr};
    const float* b128[2] = {nullptr, nullptr};
    const float* b2 = nullptr;
    int ne = 0, n16 = 0, n8 = 0, nb = 0;
    int x_slot = -1;

    for (int i = 0; i < n_in && i < 12; i++) {
        int sz = in_sizes[i];
        if (sz == N_NODES * DIM)      { x = (const float*)d_in[i]; x_slot = i; }
        else if (sz == N_EDGES)       { if (ne < 2)  edge[ne++] = (const int*)d_in[i]; }
        else if (sz == DIM * DIM)     { if (n16 < 4) w16[n16++] = (const float*)d_in[i]; }
        else if (sz == DIM * 64)      { if (n8 < 2)  w8[n8++]   = (const float*)d_in[i]; }
        else if (sz == DIM)           { if (nb < 2)  b128[nb++] = (const float*)d_in[i]; }
        else if (sz == 64)            { b2 = (const float*)d_in[i]; }
    }

    const float *Ws0, *Wn0, *b0, *Ws1, *Wn1, *b1, *Ws2, *Wn2;
    const int *src, *dst;
    if (x_slot == 0) {
        src = edge[0]; dst = edge[1];
        Ws0 = w16[0]; Wn0 = w16[1]; Ws1 = w16[2]; Wn1 = w16[3];
        Ws2 = w8[0];  Wn2 = w8[1];
    } else {
        dst = edge[0]; src = edge[1];
        Wn0 = w16[0]; Wn1 = w16[1]; Ws0 = w16[2]; Ws1 = w16[3];
        Wn2 = w8[0];  Ws2 = w8[1];
    }
    b0 = b128[0]; b1 = b128[1];
    float* out = (float*)d_out;

    // dynamic smem: As(128*36) + Bs(32*(OUT+8)) + bs(OUT), floats
    const int SMEM128 = (128 * 36 + 32 * 136 + 128) * 4;   // 36352 B
    const int SMEM64  = (128 * 36 + 32 * 72  + 64) * 4;    // 27904 B

    // ---- weight pre-conversion (tf32) ----
    convw_kernel<128, 0><<<(256 * 128 + 255) / 256, 256>>>(Ws0, Wn0);
    convw_kernel<128, 1><<<(256 * 128 + 255) / 256, 256>>>(Ws1, Wn1);
    convw_kernel<64,  2><<<(256 * 64  + 255) / 256, 256>>>(Ws2, Wn2);

    // ---- CSR build (by dst) ----
    const int NB = (N_NODES + 255) / 256;   // 196
    zero_count_kernel<<<NB, 256>>>();
    hist_kernel<<<(N_EDGES + 255) / 256, 256>>>(dst);
    reduce_counts_kernel<<<NB, 256>>>();
    scan_partials_kernel<<<1, 256>>>();
    block_scan_kernel<<<NB, 256>>>();
    cursor_kernel<<<NB, 256>>>();
    scatter_kernel<<<(N_EDGES + 255) / 256, 256>>>(src, dst);

    const int AGG_BLOCKS  = (N_NODES * 32 + 255) / 256;
    const int GEMM_BLOCKS = (N_NODES + 127) / 128;

    // ---- layer 0: x -> g_h1 ----
    aggregate_kernel<0><<<AGG_BLOCKS, 256>>>(x);
    gemm_tc_kernel<128, true, 0, 1, 0><<<GEMM_BLOCKS, 256, SMEM128>>>(x, b0, nullptr);

    // ---- layer 1: g_h1 -> g_h2 ----
    aggregate_kernel<1><<<AGG_BLOCKS, 256>>>(nullptr);
    gemm_tc_kernel<128, true, 1, 2, 1><<<GEMM_BLOCKS, 256, SMEM128>>>(nullptr, b1, nullptr);

    // ---- layer 2: g_h2 -> out ----
    aggregate_kernel<2><<<AGG_BLOCKS, 256>>>(nullptr);
    gemm_tc_kernel<64, false, 2, 0, 2><<<GEMM_BLOCKS, 256, SMEM64>>>(nullptr, b2, out);
}